// round 6
// baseline (speedup 1.0000x reference)
#include <cuda_runtime.h>
#include <cstdint>

#define K_DIM 8192
#define M_DIM 8192
#define KGRP (K_DIM / 16)            // 512 kgroups (16 k each) per row
#define KC 8                         // pass2 k-chunks
#define CHUNKK (K_DIM / KC)          // 1024
#define BAND_CAP (2 * 1024 * 1024)

typedef unsigned long long ull;

// ---------------- static device scratch ----------------
__device__ float4 g_xt4[K_DIM * 2];           // x_hat transposed [K][8] (256 KB)
__device__ float g_ssum[256];                 // sample partials
__device__ float g_bsum[1024];                // exact |W| partials
__device__ float g_inv64;                     // 64 / t_hat
__device__ float g_thresh, g_wdeq;            // exact threshold, dequant
__device__ unsigned g_bandcnt;
__device__ uint2 g_band[BAND_CAP];            // (row*8192+k, bits(w)); gaps zeroed
__device__ float g_corr[M_DIM * 8];
__device__ unsigned g_code[(size_t)KGRP * M_DIM];   // 2-bit codes, [kgroup][row], 16 MB
__device__ ull g_part[(size_t)M_DIM * KC * 4];      // f32x2 partials

// ---------------- helpers ----------------
__device__ __forceinline__ void fma2(ull& acc, ull x, ull q) {
    asm("fma.rn.f32x2 %0, %1, %2, %0;" : "+l"(acc) : "l"(x), "l"(q));
}
__device__ __forceinline__ void add2(ull& acc, ull x) {
    asm("add.rn.f32x2 %0, %1, %0;" : "+l"(acc) : "l"(x));
}

// ---------------- kernel 0: zero band buffer + corr ----------------
__global__ void init_kernel() {
    unsigned gid = blockIdx.x * 256 + threadIdx.x;     // 0..524287
    uint4 z = make_uint4(0, 0, 0, 0);
    uint4* b4 = (uint4*)g_band;                        // 1M uint4
    b4[gid] = z;
    b4[gid + 524288] = z;
    if (gid < 16384) ((uint4*)g_corr)[gid] = z;        // 64K floats
}

// ---------------- kernel 1: activation per-group int8 quantization ----------------
__global__ void quant_x_kernel(const float* __restrict__ x) {
    int gw = (blockIdx.x * blockDim.x + threadIdx.x) >> 5;
    int lane = threadIdx.x & 31;
    int n = gw >> 7;
    int g = gw & 127;
    int k0 = g * 64 + lane;
    float a = x[n * K_DIM + k0];
    float b = x[n * K_DIM + k0 + 32];
    float mx = fmaxf(fabsf(a), fabsf(b));
#pragma unroll
    for (int off = 16; off; off >>= 1)
        mx = fmaxf(mx, __shfl_xor_sync(0xffffffffu, mx, off));
    float s = fmaxf(__fdiv_rn(mx, 127.0f), 1e-8f);
    float ah = rintf(__fdiv_rn(a, s)) * s;
    float bh = rintf(__fdiv_rn(b, s)) * s;
    float* xt = (float*)g_xt4;
    xt[k0 * 8 + n] = ah;
    xt[(k0 + 32) * 8 + n] = bh;
}

// ---------------- kernel 2: sampled |W| estimate (first 16 MB) ----------------
__global__ void sample_kernel(const float4* __restrict__ W4) {
    __shared__ float sm[8];
    int t0 = blockIdx.x * 256 + threadIdx.x;
    const int stride = 256 * 256;
    float s = 0.f;
#pragma unroll 4
    for (int it = 0; it < 16; it++) {
        float4 v = __ldg(W4 + t0 + (size_t)it * stride);
        s += fabsf(v.x) + fabsf(v.y) + fabsf(v.z) + fabsf(v.w);
    }
#pragma unroll
    for (int off = 16; off; off >>= 1) s += __shfl_xor_sync(0xffffffffu, s, off);
    int lane = threadIdx.x & 31, w = threadIdx.x >> 5;
    if (lane == 0) sm[w] = s;
    __syncthreads();
    if (threadIdx.x == 0) {
        float tot = 0.f;
#pragma unroll
        for (int i = 0; i < 8; i++) tot += sm[i];
        g_ssum[blockIdx.x] = tot;
    }
}

// ---------------- kernel 3: t-hat -> inv scale; reset counter ----------------
__global__ void sample_finalize_kernel() {
    __shared__ float sm[8];
    int tid = threadIdx.x;
    float s = g_ssum[tid];
#pragma unroll
    for (int off = 16; off; off >>= 1) s += __shfl_xor_sync(0xffffffffu, s, off);
    int lane = tid & 31, w = tid >> 5;
    if (lane == 0) sm[w] = s;
    __syncthreads();
    if (tid == 0) {
        float tot = 0.f;
#pragma unroll
        for (int i = 0; i < 8; i++) tot += sm[i];
        float mean_s = tot * (1.0f / 4194304.0f);
        float t_hat = 0.5f * fmaxf(mean_s, 1e-5f);
        g_inv64 = __fdiv_rn(64.0f, t_hat);
        g_bandcnt = 0u;
    }
}

// ---------------- kernel 4: PASS 1 — stream W once: abs-sum + 2-bit codes + band list ----------------
// One warp per row. Coalesced float4 reads; codes packed across 4 lanes via shfl;
// band entries (ri in [63,65]) pushed with warp-aggregated chunk-128 allocation.
__global__ void __launch_bounds__(256) pass1_kernel(const float* __restrict__ W) {
    __shared__ float sm[8];
    const float inv64 = g_inv64;
    const unsigned FULL = 0xffffffffu;
    int lane = threadIdx.x & 31, warp = threadIdx.x >> 5;
    int row = blockIdx.x * 8 + warp;
    const float4* Wr = (const float4*)(W + (size_t)row * K_DIM);
    const unsigned lmlt = (1u << lane) - 1u;

    float asum = 0.f, chunk = 0.f;
    unsigned wbase = 0, wleft = 0;

#pragma unroll 2
    for (int i = 0; i < 64; i++) {
        float4 v = Wr[i * 32 + lane];
        chunk += (fabsf(v.x) + fabsf(v.y)) + (fabsf(v.z) + fabsf(v.w));
        if ((i & 15) == 15) { asum += chunk; chunk = 0.f; }

        float we[4] = {v.x, v.y, v.z, v.w};
        unsigned byte = 0;
#pragma unroll
        for (int e = 0; e < 4; e++) {
            float w = we[e];
            int ri = __float2int_rn(fabsf(w) * inv64);
            bool band = (ri >= 63) && (ri <= 65);
            unsigned code = (ri >= 66) ? ((w < 0.f) ? 3u : 1u) : 0u;
            byte |= code << (2 * e);
            unsigned bm = __ballot_sync(FULL, band);
            if (bm) {
                unsigned c = (unsigned)__popc(bm);
                if (wleft < c) {
                    unsigned nb = 0;
                    if (lane == 0) nb = atomicAdd(&g_bandcnt, 128u);
                    nb = __shfl_sync(FULL, nb, 0);
                    wbase = nb; wleft = 128u;
                }
                if (band) {
                    unsigned pos = wbase + (unsigned)__popc(bm & lmlt);
                    if (pos < BAND_CAP) {
                        int k = i * 128 + lane * 4 + e;
                        g_band[pos] = make_uint2((unsigned)(row * K_DIM + k),
                                                 __float_as_uint(w));
                    }
                }
                wbase += c; wleft -= c;
            }
        }
        // pack 4 lanes' bytes -> one uint32 (k-ascending byte order)
        unsigned p1 = __shfl_xor_sync(FULL, byte, 1);
        unsigned h = (lane & 1) ? ((byte << 8) | p1) : (byte | (p1 << 8));
        unsigned p2 = __shfl_xor_sync(FULL, h, 2);
        unsigned word = (lane & 2) ? ((h << 16) | p2) : (h | (p2 << 16));
        if ((lane & 3) == 0) {
            int kg = i * 8 + (lane >> 2);
            g_code[(size_t)kg * M_DIM + row] = word;
        }
    }
    asum += chunk;

#pragma unroll
    for (int off = 16; off; off >>= 1) asum += __shfl_xor_sync(FULL, asum, off);
    if (lane == 0) sm[warp] = asum;
    __syncthreads();
    if (threadIdx.x == 0) {
        float tot = 0.f;
#pragma unroll
        for (int i = 0; i < 8; i++) tot += sm[i];
        g_bsum[blockIdx.x] = tot;
    }
}

// ---------------- kernel 5: exact mean -> exact threshold ----------------
__global__ void finalize_mean_kernel() {
    __shared__ float sm[8];
    int tid = threadIdx.x;
    float s = g_bsum[tid] + g_bsum[tid + 256] + g_bsum[tid + 512] + g_bsum[tid + 768];
#pragma unroll
    for (int off = 16; off; off >>= 1) s += __shfl_xor_sync(0xffffffffu, s, off);
    int lane = tid & 31, w = tid >> 5;
    if (lane == 0) sm[w] = s;
    __syncthreads();
    if (tid == 0) {
        float tot = 0.f;
#pragma unroll
        for (int i = 0; i < 8; i++) tot += sm[i];
        float mean = tot * (1.0f / 67108864.0f);
        float m = fmaxf(mean, 1e-5f);
        float s_w = __fdiv_rn(1.0f, m);
        float wdeq = __fdiv_rn(1.0f, s_w);
        g_wdeq = wdeq;
        g_thresh = 0.5f * wdeq;
    }
}

// ---------------- kernel 6: PASS 2 — GEMV on 2-bit codes ----------------
// Block: 64 rows x 1024-k chunk. Lane owns rows (lane, lane+32); warp w handles
// kgroups w, w+8, ..., w+56 of the chunk. x chunk staged in smem (32 KB).
__global__ void __launch_bounds__(256) pass2_kernel() {
    __shared__ float4 xs4[2048];                 // 32 KB: x for this k-chunk
    int tid = threadIdx.x, lane = tid & 31, warp = tid >> 5;
    int rt = blockIdx.x >> 3;                    // 0..127 row tiles
    int kc = blockIdx.x & 7;                     // 0..7 chunks
    int rowbase = rt * 64;
    int k0 = kc * CHUNKK;

#pragma unroll
    for (int i = tid; i < 2048; i += 256) xs4[i] = g_xt4[k0 * 2 + i];
    __syncthreads();

    const ulonglong2* X = (const ulonglong2*)xs4;
    const unsigned* codeA = g_code + (size_t)(kc * 64) * M_DIM + rowbase + lane;

    ull a0 = 0, a1 = 0, a2 = 0, a3 = 0;
    ull b0 = 0, b1 = 0, b2 = 0, b3 = 0;

#pragma unroll 2
    for (int g8 = 0; g8 < 8; g8++) {
        int kgl = g8 * 8 + warp;                 // chunk-local kgroup 0..63
        unsigned ca = codeA[(size_t)kgl * M_DIM];
        unsigned cb = codeA[(size_t)kgl * M_DIM + 32];
        int kk = kgl * 16;                       // chunk-local k
#pragma unroll
        for (int j = 0; j < 16; j++) {
            int qa = ((int)(ca << (30 - 2 * j))) >> 30;   // -1/0/+1
            int qb = ((int)(cb << (30 - 2 * j))) >> 30;
            float fa = (float)qa, fb = (float)qb;
            ull qa2, qb2;
            asm("mov.b64 %0, {%1,%1};" : "=l"(qa2) : "f"(fa));
            asm("mov.b64 %0, {%1,%1};" : "=l"(qb2) : "f"(fb));
            ulonglong2 x0 = X[(kk + j) * 2];
            ulonglong2 x1 = X[(kk + j) * 2 + 1];
            fma2(a0, x0.x, qa2); fma2(a1, x0.y, qa2);
            fma2(a2, x1.x, qa2); fma2(a3, x1.y, qa2);
            fma2(b0, x0.x, qb2); fma2(b1, x0.y, qb2);
            fma2(b2, x1.x, qb2); fma2(b3, x1.y, qb2);
        }
    }

    // ---- in-block cross-warp reduction: 8 partials/row -> 1 ----
    __syncthreads();
    ulonglong2* s2 = (ulonglong2*)xs4;
    s2[(warp * 64 + lane) * 2]          = make_ulonglong2(a0, a1);
    s2[(warp * 64 + lane) * 2 + 1]      = make_ulonglong2(a2, a3);
    s2[(warp * 64 + lane + 32) * 2]     = make_ulonglong2(b0, b1);
    s2[(warp * 64 + lane + 32) * 2 + 1] = make_ulonglong2(b2, b3);
    __syncthreads();
    if (tid < 64) {
        ull r0 = 0, r1 = 0, r2 = 0, r3 = 0;
#pragma unroll
        for (int w = 0; w < 8; w++) {
            ulonglong2 u0 = s2[(w * 64 + tid) * 2];
            ulonglong2 u1 = s2[(w * 64 + tid) * 2 + 1];
            add2(r0, u0.x); add2(r1, u0.y);
            add2(r2, u1.x); add2(r3, u1.y);
        }
        ulonglong2* P = (ulonglong2*)g_part;
        size_t p = ((size_t)(rowbase + tid) * KC + kc) * 2;
        P[p]     = make_ulonglong2(r0, r1);
        P[p + 1] = make_ulonglong2(r2, r3);
    }
}

// ---------------- kernel 7: replay band entries against exact threshold ----------------
__global__ void correction_kernel() {
    unsigned cnt = g_bandcnt;
    if (cnt > BAND_CAP) cnt = BAND_CAP;
    float th = g_thresh;
    for (unsigned i = blockIdx.x * 256 + threadIdx.x; i < cnt; i += 256 * 256) {
        uint2 e = g_band[i];
        float w = __uint_as_float(e.y);
        if (fabsf(w) > th) {                     // zeroed gaps: w=0 never passes
            float sgn = copysignf(1.0f, w);
            unsigned idx = e.x;
            int m = idx >> 13, k = idx & 8191;
            float4 x0 = g_xt4[k * 2], x1 = g_xt4[k * 2 + 1];
            float* c = g_corr + m * 8;
            atomicAdd(c + 0, sgn * x0.x);
            atomicAdd(c + 1, sgn * x0.y);
            atomicAdd(c + 2, sgn * x0.z);
            atomicAdd(c + 3, sgn * x0.w);
            atomicAdd(c + 4, sgn * x1.x);
            atomicAdd(c + 5, sgn * x1.y);
            atomicAdd(c + 6, sgn * x1.z);
            atomicAdd(c + 7, sgn * x1.w);
        }
    }
}

// ---------------- kernel 8: reduce partials + corrections, apply w_deq ----------------
__global__ void finalize_out_kernel(float* __restrict__ out) {
    int m = blockIdx.x * blockDim.x + threadIdx.x;
    const float4* p = (const float4*)g_part + (size_t)m * KC * 2;
    float s0 = 0, s1 = 0, s2 = 0, s3 = 0, s4 = 0, s5 = 0, s6 = 0, s7 = 0;
#pragma unroll
    for (int ks = 0; ks < KC; ks++) {
        float4 A = p[ks * 2];
        float4 B = p[ks * 2 + 1];
        s0 += A.x; s1 += A.y; s2 += A.z; s3 += A.w;
        s4 += B.x; s5 += B.y; s6 += B.z; s7 += B.w;
    }
    const float* c = g_corr + m * 8;
    float wd = g_wdeq;
    out[0 * M_DIM + m] = wd * (s0 + c[0]);
    out[1 * M_DIM + m] = wd * (s1 + c[1]);
    out[2 * M_DIM + m] = wd * (s2 + c[2]);
    out[3 * M_DIM + m] = wd * (s3 + c[3]);
    out[4 * M_DIM + m] = wd * (s4 + c[4]);
    out[5 * M_DIM + m] = wd * (s5 + c[5]);
    out[6 * M_DIM + m] = wd * (s6 + c[6]);
    out[7 * M_DIM + m] = wd * (s7 + c[7]);
}

// ---------------- launch ----------------
extern "C" void kernel_launch(void* const* d_in, const int* in_sizes, int n_in,
                              void* d_out, int out_size) {
    const float* x = (const float*)d_in[0];    // [8, 8192]
    const float* W = (const float*)d_in[1];    // [8192, 8192]
    float* out = (float*)d_out;                // [8, 8192]

    init_kernel<<<2048, 256>>>();                        // zero band gaps + corr
    quant_x_kernel<<<128, 256>>>(x);                     // x_hat (transposed)
    sample_kernel<<<256, 256>>>((const float4*)W);       // t-hat sample
    sample_finalize_kernel<<<1, 256>>>();                // inv scale + counter reset
    pass1_kernel<<<1024, 256>>>(W);                      // 256 MB: sum|W| + codes + band
    pass2_kernel<<<1024, 256>>>();                       // GEMV on 2-bit codes
    finalize_mean_kernel<<<1, 256>>>();                  // exact threshold
    correction_kernel<<<256, 256>>>();                   // band replay
    finalize_out_kernel<<<64, 128>>>(out);               // reduce + corr + scale
}

// round 7
// speedup vs baseline: 1.7018x; 1.7018x over previous
#include <cuda_runtime.h>
#include <cstdint>

#define K_DIM 8192
#define M_DIM 8192

// gemv tiling (R3-proven)
#define ROWTILE 64
#define KC 4
#define CHUNK (K_DIM / KC)          // 2048
#define SLICE_K 64
#define NSLICES (CHUNK / SLICE_K)   // 32
#define BUF_FLOATS 4608             // W 64*64 + X 64*8
#define NBUF 3
#define SMEM_BYTES (NBUF * BUF_FLOATS * 4)   // 55296

#define SCAP 128                    // per-block smem band slots
#define BAND_CAP (1024 * 1024)

typedef unsigned long long ull;

// ---------------- static device scratch ----------------
__device__ float4 g_xt4[K_DIM * 2];            // x_hat transposed [K][8] (256 KB)
__device__ float g_ssum[256];                  // sample partials
__device__ float g_bsum[512];                  // exact |W| partials (per gemv block)
__device__ float g_tlo, g_thi;                 // conservative band bounds
__device__ float g_thresh, g_wdeq;             // exact threshold, dequant
__device__ unsigned g_bandcnt;
__device__ uint2 g_band[BAND_CAP];             // (row*8192+k, bits(w))
__device__ float g_corr[M_DIM * 8];            // correction accumulators (zeroed in quant_x)
__device__ ull g_part[(size_t)M_DIM * KC * 4]; // f32x2 partials (1 MB)

// ---------------- helpers ----------------
__device__ __forceinline__ void fma2(ull& acc, ull x, ull q) {
    asm("fma.rn.f32x2 %0, %1, %2, %0;" : "+l"(acc) : "l"(x), "l"(q));
}
__device__ __forceinline__ void add2(ull& acc, ull x) {
    asm("add.rn.f32x2 %0, %1, %0;" : "+l"(acc) : "l"(x));
}
__device__ __forceinline__ ull qdup(float q) {
    ull q2;
    asm("mov.b64 %0, {%1, %1};" : "=l"(q2) : "f"(q));
    return q2;
}
__device__ __forceinline__ void cpasync16(void* smem_dst, const void* gsrc) {
    unsigned int sa = (unsigned int)__cvta_generic_to_shared(smem_dst);
    asm volatile("cp.async.cg.shared.global [%0], [%1], 16;" :: "r"(sa), "l"(gsrc));
}
__device__ __forceinline__ void cp_commit() { asm volatile("cp.async.commit_group;"); }
__device__ __forceinline__ void cp_wait1()  { asm volatile("cp.async.wait_group 1;"); }

// ---------------- kernel 1: activation quant (+ zero corr buffer) ----------------
__global__ void quant_x_kernel(const float* __restrict__ x) {
    int gid = blockIdx.x * blockDim.x + threadIdx.x;   // 0..32767
    g_corr[gid] = 0.f;
    g_corr[gid + 32768] = 0.f;
    int gw = gid >> 5;
    int lane = threadIdx.x & 31;
    int n = gw >> 7;
    int g = gw & 127;
    int k0 = g * 64 + lane;
    float a = x[n * K_DIM + k0];
    float b = x[n * K_DIM + k0 + 32];
    float mx = fmaxf(fabsf(a), fabsf(b));
#pragma unroll
    for (int off = 16; off; off >>= 1)
        mx = fmaxf(mx, __shfl_xor_sync(0xffffffffu, mx, off));
    float s = fmaxf(__fdiv_rn(mx, 127.0f), 1e-8f);
    float ah = rintf(__fdiv_rn(a, s)) * s;
    float bh = rintf(__fdiv_rn(b, s)) * s;
    float* xt = (float*)g_xt4;
    xt[k0 * 8 + n] = ah;
    xt[(k0 + 32) * 8 + n] = bh;
}

// ---------------- kernel 2: sampled |W| estimate (first 16 MB) ----------------
__global__ void sample_kernel(const float4* __restrict__ W4) {
    __shared__ float sm[8];
    int t0 = blockIdx.x * 256 + threadIdx.x;
    const int stride = 256 * 256;
    float s = 0.f;
#pragma unroll 4
    for (int it = 0; it < 16; it++) {
        float4 v = __ldg(W4 + t0 + (size_t)it * stride);
        s += fabsf(v.x) + fabsf(v.y) + fabsf(v.z) + fabsf(v.w);
    }
#pragma unroll
    for (int off = 16; off; off >>= 1) s += __shfl_xor_sync(0xffffffffu, s, off);
    int lane = threadIdx.x & 31, w = threadIdx.x >> 5;
    if (lane == 0) sm[w] = s;
    __syncthreads();
    if (threadIdx.x == 0) {
        float tot = 0.f;
#pragma unroll
        for (int i = 0; i < 8; i++) tot += sm[i];
        g_ssum[blockIdx.x] = tot;
    }
}

// ---------------- kernel 3: t-hat -> band bounds; reset counter ----------------
__global__ void sample_finalize_kernel() {
    __shared__ float sm[8];
    int tid = threadIdx.x;
    float s = g_ssum[tid];
#pragma unroll
    for (int off = 16; off; off >>= 1) s += __shfl_xor_sync(0xffffffffu, s, off);
    int lane = tid & 31, w = tid >> 5;
    if (lane == 0) sm[w] = s;
    __syncthreads();
    if (tid == 0) {
        float tot = 0.f;
#pragma unroll
        for (int i = 0; i < 8; i++) tot += sm[i];
        float mean_s = tot * (1.0f / 4194304.0f);
        float t_hat = 0.5f * fmaxf(mean_s, 1e-5f);
        g_tlo = t_hat * 0.998f;
        g_thi = t_hat * 1.002f;
        g_bandcnt = 0u;
    }
}

// ---------------- kernel 4: SINGLE fused pass over W ----------------
// R3 gemv skeleton + exact |W| partial sums + scalar band capture (no warp collectives).
__global__ void __launch_bounds__(256, 4) gemv_fused_kernel(const float* __restrict__ W) {
    extern __shared__ float smem[];
    __shared__ uint2 s_band[SCAP];
    __shared__ int s_cnt;
    __shared__ unsigned s_gbase;

    const float tlo = g_tlo, thi = g_thi;
    const int tid = threadIdx.x;
    const int lane = tid & 31, warp = tid >> 5;
    const int rt = blockIdx.x >> 2;            // 0..127 row tiles
    const int kc = blockIdx.x & 3;             // 0..3 k chunks
    const int rowbase = rt * ROWTILE;
    const int k0 = kc * CHUNK;
    const float* xt = (const float*)g_xt4;
    if (tid == 0) s_cnt = 0;

    auto stage = [&](int s) {
        float* buf = smem + (s % NBUF) * BUF_FLOATS;
        float* bufX = buf + ROWTILE * SLICE_K;
        int base_k = k0 + s * SLICE_K;
#pragma unroll
        for (int i = 0; i < 4; i++) {
            int idx = tid + i * 256;
            int r = idx >> 4, c = idx & 15;
            cpasync16(buf + r * SLICE_K + ((c ^ (r & 7)) << 2),
                      W + (size_t)(rowbase + r) * K_DIM + base_k + c * 4);
        }
        if (tid < 128) cpasync16(bufX + tid * 4, xt + (size_t)base_k * 8 + tid * 4);
    };

    ull a0 = 0, a1 = 0, a2 = 0, a3 = 0;
    ull b0 = 0, b1 = 0, b2 = 0, b3 = 0;
    float sabs = 0.f;

    stage(0); cp_commit();
    stage(1); cp_commit();

    const int sw = lane & 7;
    for (int s = 0; s < NSLICES; s++) {
        cp_wait1();
        __syncthreads();
        if (s + 2 < NSLICES) stage(s + 2);
        cp_commit();

        const float* buf = smem + (s % NBUF) * BUF_FLOATS;
        const ulonglong2* Xb = (const ulonglong2*)(buf + ROWTILE * SLICE_K);
#pragma unroll
        for (int step = 0; step < 2; step++) {
            int kk = warp * 8 + step * 4;
            int ch = kk >> 2;
            float4 wa = *(const float4*)(buf + lane * SLICE_K + ((ch ^ sw) << 2));
            float4 wb = *(const float4*)(buf + (lane + 32) * SLICE_K + ((ch ^ sw) << 2));
            float wae[4] = {wa.x, wa.y, wa.z, wa.w};
            float wbe[4] = {wb.x, wb.y, wb.z, wb.w};
#pragma unroll
            for (int e = 0; e < 4; e++) {
                float va = wae[e], vb = wbe[e];
                float ava = fabsf(va), avb = fabsf(vb);
                sabs += ava + avb;
                bool pa = ava > thi, pb = avb > thi;
                ull qa = qdup(pa ? copysignf(1.0f, va) : 0.0f);
                ull qb = qdup(pb ? copysignf(1.0f, vb) : 0.0f);
                ulonglong2 x0 = Xb[(kk + e) * 2];
                ulonglong2 x1 = Xb[(kk + e) * 2 + 1];
                fma2(a0, x0.x, qa); fma2(a1, x0.y, qa);
                fma2(a2, x1.x, qa); fma2(a3, x1.y, qa);
                fma2(b0, x0.x, qb); fma2(b1, x0.y, qb);
                fma2(b2, x1.x, qb); fma2(b3, x1.y, qb);
                // rare band capture — scalar path, no warp collectives
                if ((ava > tlo) && !pa) {
                    int k = k0 + s * SLICE_K + kk + e;
                    int slot = atomicAdd(&s_cnt, 1);
                    uint2 ent = make_uint2((unsigned)((rowbase + lane) * K_DIM + k),
                                           __float_as_uint(va));
                    if (slot < SCAP) s_band[slot] = ent;
                    else {
                        unsigned gp = atomicAdd(&g_bandcnt, 1u);
                        if (gp < BAND_CAP) g_band[gp] = ent;
                    }
                }
                if ((avb > tlo) && !pb) {
                    int k = k0 + s * SLICE_K + kk + e;
                    int slot = atomicAdd(&s_cnt, 1);
                    uint2 ent = make_uint2((unsigned)((rowbase + lane + 32) * K_DIM + k),
                                           __float_as_uint(vb));
                    if (slot < SCAP) s_band[slot] = ent;
                    else {
                        unsigned gp = atomicAdd(&g_bandcnt, 1u);
                        if (gp < BAND_CAP) g_band[gp] = ent;
                    }
                }
            }
        }
    }

    // ---- block reductions: abs-sum + 8->1 partials ----
    __syncthreads();
#pragma unroll
    for (int off = 16; off; off >>= 1) sabs += __shfl_xor_sync(0xffffffffu, sabs, off);
    float* absm = smem + NBUF * BUF_FLOATS - 16;   // top of dynamic smem (clear of s2 region)
    if (lane == 0) absm[warp] = sabs;

    ulonglong2* s2 = (ulonglong2*)smem;
    s2[(warp * 64 + lane) * 2]          = make_ulonglong2(a0, a1);
    s2[(warp * 64 + lane) * 2 + 1]      = make_ulonglong2(a2, a3);
    s2[(warp * 64 + lane + 32) * 2]     = make_ulonglong2(b0, b1);
    s2[(warp * 64 + lane + 32) * 2 + 1] = make_ulonglong2(b2, b3);
    __syncthreads();

    if (tid == 0) {
        float tot = 0.f;
#pragma unroll
        for (int i = 0; i < 8; i++) tot += absm[i];
        g_bsum[blockIdx.x] = tot;
        int cnt = s_cnt; if (cnt > SCAP) cnt = SCAP;
        s_gbase = atomicAdd(&g_bandcnt, (unsigned)cnt);
    }
    if (tid < 64) {
        ull r0 = 0, r1 = 0, r2 = 0, r3 = 0;
#pragma unroll
        for (int w = 0; w < 8; w++) {
            ulonglong2 u0 = s2[(w * 64 + tid) * 2];
            ulonglong2 u1 = s2[(w * 64 + tid) * 2 + 1];
            add2(r0, u0.x); add2(r1, u0.y);
            add2(r2, u1.x); add2(r3, u1.y);
        }
        ulonglong2* P = (ulonglong2*)g_part;
        size_t p = ((size_t)(rowbase + tid) * KC + kc) * 2;
        P[p]     = make_ulonglong2(r0, r1);
        P[p + 1] = make_ulonglong2(r2, r3);
    }
    __syncthreads();
    // flush smem band list
    int cnt = s_cnt; if (cnt > SCAP) cnt = SCAP;
    for (int i = tid; i < cnt; i += 256) {
        unsigned gp = s_gbase + (unsigned)i;
        if (gp < BAND_CAP) g_band[gp] = s_band[i];
    }
}

// ---------------- kernel 5: exact mean -> exact threshold ----------------
__global__ void finalize_mean_kernel() {
    __shared__ float sm[8];
    int tid = threadIdx.x;
    float s = g_bsum[tid] + g_bsum[tid + 256];
#pragma unroll
    for (int off = 16; off; off >>= 1) s += __shfl_xor_sync(0xffffffffu, s, off);
    int lane = tid & 31, w = tid >> 5;
    if (lane == 0) sm[w] = s;
    __syncthreads();
    if (tid == 0) {
        float tot = 0.f;
#pragma unroll
        for (int i = 0; i < 8; i++) tot += sm[i];
        float mean = tot * (1.0f / 67108864.0f);
        float m = fmaxf(mean, 1e-5f);
        float s_w = __fdiv_rn(1.0f, m);
        float wdeq = __fdiv_rn(1.0f, s_w);
        g_wdeq = wdeq;
        g_thresh = 0.5f * wdeq;
    }
}

// ---------------- kernel 6: replay band entries against exact threshold ----------------
__global__ void correction_kernel() {
    unsigned cnt = g_bandcnt;
    if (cnt > BAND_CAP) cnt = BAND_CAP;
    float th = g_thresh;
    for (unsigned i = blockIdx.x * 256 + threadIdx.x; i < cnt; i += 256 * 256) {
        uint2 e = g_band[i];
        float w = __uint_as_float(e.y);
        if (fabsf(w) > th) {
            float sgn = copysignf(1.0f, w);
            unsigned idx = e.x;
            int m = idx >> 13, k = idx & 8191;
            float4 x0 = g_xt4[k * 2], x1 = g_xt4[k * 2 + 1];
            float* c = g_corr + m * 8;
            atomicAdd(c + 0, sgn * x0.x);
            atomicAdd(c + 1, sgn * x0.y);
            atomicAdd(c + 2, sgn * x0.z);
            atomicAdd(c + 3, sgn * x0.w);
            atomicAdd(c + 4, sgn * x1.x);
            atomicAdd(c + 5, sgn * x1.y);
            atomicAdd(c + 6, sgn * x1.z);
            atomicAdd(c + 7, sgn * x1.w);
        }
    }
}

// ---------------- kernel 7: reduce partials + corrections, apply w_deq ----------------
__global__ void finalize_out_kernel(float* __restrict__ out) {
    int m = blockIdx.x * blockDim.x + threadIdx.x;
    const float4* p = (const float4*)g_part + (size_t)m * KC * 2;
    float s0 = 0, s1 = 0, s2 = 0, s3 = 0, s4 = 0, s5 = 0, s6 = 0, s7 = 0;
#pragma unroll
    for (int ks = 0; ks < KC; ks++) {
        float4 A = p[ks * 2];
        float4 B = p[ks * 2 + 1];
        s0 += A.x; s1 += A.y; s2 += A.z; s3 += A.w;
        s4 += B.x; s5 += B.y; s6 += B.z; s7 += B.w;
    }
    const float* c = g_corr + m * 8;
    float wd = g_wdeq;
    out[0 * M_DIM + m] = wd * (s0 + c[0]);
    out[1 * M_DIM + m] = wd * (s1 + c[1]);
    out[2 * M_DIM + m] = wd * (s2 + c[2]);
    out[3 * M_DIM + m] = wd * (s3 + c[3]);
    out[4 * M_DIM + m] = wd * (s4 + c[4]);
    out[5 * M_DIM + m] = wd * (s5 + c[5]);
    out[6 * M_DIM + m] = wd * (s6 + c[6]);
    out[7 * M_DIM + m] = wd * (s7 + c[7]);
}

// ---------------- launch ----------------
extern "C" void kernel_launch(void* const* d_in, const int* in_sizes, int n_in,
                              void* d_out, int out_size) {
    const float* x = (const float*)d_in[0];    // [8, 8192]
    const float* W = (const float*)d_in[1];    // [8192, 8192]
    float* out = (float*)d_out;                // [8, 8192]

    static bool attr_done = false;
    if (!attr_done) {
        cudaFuncSetAttribute(gemv_fused_kernel, cudaFuncAttributeMaxDynamicSharedMemorySize,
                             SMEM_BYTES);
        attr_done = true;
    }

    quant_x_kernel<<<128, 256>>>(x);                     // x_hat + zero corr
    sample_kernel<<<256, 256>>>((const float4*)W);       // t-hat sample (16 MB)
    sample_finalize_kernel<<<1, 256>>>();                // band bounds + counter reset
    gemv_fused_kernel<<<512, 256, SMEM_BYTES>>>(W);      // ONE 256 MB pass
    finalize_mean_kernel<<<1, 256>>>();                  // exact threshold
    correction_kernel<<<256, 256>>>();                   // band replay
    finalize_out_kernel<<<64, 128>>>(out);               // reduce + corr + scale
}